// round 14
// baseline (speedup 1.0000x reference)
#include <cuda_runtime.h>
#include <cuda_fp16.h>
#include <cstdint>

// ============================================================================
// y[m,n] = sum_k x[m,k] * ((q[k,n]-zp)*scale) + bias[n]
// Decomposition: W = scale*(q-128) + scale*(128-zp);  (q-128) exact in fp16.
// R14: persistent stream-K. 296 persistent CTAs (2/SM), each consumes an even
//   share of the 65536 global K-chunks through the R13 mbarrier ring, which
//   now pipelines ACROSS tile boundaries (no per-tile prologue drain, epilogue
//   overlapped with next tile's loads). Wave-tail 13.5% -> 0.5% imbalance.
//   Split tiles (~295/1024) accumulate via red.global.add.f32 into an output
//   pre-initialized by prep with bias + scale*(128-zp)*rowsum; whole tiles
//   use direct stores of the full expression (consistent with pre-init).
// ============================================================================

#define M_TOT 4096
#define N_TOT 4096
#define K_TOT 4096

__device__ __align__(256) __half g_A[(size_t)M_TOT * K_TOT]; // x fp16 [M,K]
__device__ __align__(256) __half g_B[(size_t)N_TOT * K_TOT]; // (q-128) fp16 [N,K]
__device__ float g_rowsum[M_TOT];

// ---------------------------------------------------------------------------
__device__ __forceinline__ uint32_t smem_to_u32(const void* p) {
    uint32_t a;
    asm("{ .reg .u64 t; cvta.to.shared.u64 t, %1; cvt.u32.u64 %0, t; }"
        : "=r"(a) : "l"(p));
    return a;
}

__device__ __forceinline__ uint32_t h2_bits(__half2 h) {
    return *reinterpret_cast<uint32_t*>(&h);
}

#define SWZ(o) ((o) ^ (((o) >> 3) & 0x70))

#define CP_ASYNC_16(dst, src) \
    asm volatile("cp.async.cg.shared.global [%0], [%1], 16;" \
                 :: "r"(dst), "l"(src) : "memory")

#define MBAR_INIT(addr, cnt) \
    asm volatile("mbarrier.init.shared.b64 [%0], %1;" \
                 :: "r"((uint32_t)(addr)), "r"((uint32_t)(cnt)) : "memory")
#define MBAR_ARRIVE(addr) \
    asm volatile("mbarrier.arrive.shared.b64 _, [%0];" \
                 :: "r"((uint32_t)(addr)) : "memory")
#define CP_ASYNC_MBAR_ARRIVE(addr) \
    asm volatile("cp.async.mbarrier.arrive.noinc.shared.b64 [%0];" \
                 :: "r"((uint32_t)(addr)) : "memory")

#define MBAR_WAIT(mbar, parity) do {                                          \
    uint32_t _m = (uint32_t)(mbar);                                           \
    uint32_t _p = (uint32_t)(parity);                                         \
    uint32_t _done;                                                           \
    asm volatile(                                                             \
        "{\n\t.reg .pred p;\n\t"                                              \
        "mbarrier.try_wait.parity.acquire.cta.shared::cta.b64 p, [%1], %2;\n\t" \
        "selp.b32 %0, 1, 0, p;\n\t}"                                          \
        : "=r"(_done) : "r"(_m), "r"(_p) : "memory");                         \
    if (!_done) {                                                             \
        asm volatile(                                                         \
            "{\n\t.reg .pred P1;\n\t"                                         \
            "WL_%=:\n\t"                                                      \
            "mbarrier.try_wait.parity.acquire.cta.shared::cta.b64 P1, [%0], %1, 0x989680;\n\t" \
            "@P1 bra.uni WD_%=;\n\t"                                          \
            "bra.uni WL_%=;\n\t"                                              \
            "WD_%=:\n\t}"                                                     \
            :: "r"(_m), "r"(_p) : "memory");                                  \
    }                                                                         \
} while (0)

#define LDSM_X4(R0, R1, R2, R3, ADDR) \
    asm volatile("ldmatrix.sync.aligned.m8n8.x4.shared.b16 {%0,%1,%2,%3}, [%4];" \
                 : "=r"(R0), "=r"(R1), "=r"(R2), "=r"(R3) : "r"(ADDR))

#define MMA16816(C, A0, A1, A2, A3, B0, B1) \
    asm volatile("mma.sync.aligned.m16n8k16.row.col.f32.f16.f16.f32 " \
                 "{%0,%1,%2,%3}, {%4,%5,%6,%7}, {%8,%9}, {%0,%1,%2,%3};" \
                 : "+f"((C)[0]), "+f"((C)[1]), "+f"((C)[2]), "+f"((C)[3]) \
                 : "r"(A0), "r"(A1), "r"(A2), "r"(A3), "r"(B0), "r"(B1))

#define REDG_ADD_F32(addr, val) \
    asm volatile("red.global.add.f32 [%0], %1;" :: "l"(addr), "f"(val) : "memory")

// ---------------------------------------------------------------------------
// Merged prep (one launch).
//  blocks [0, 4096): x row -> fp16 + rowsum + out pre-init (bias + affine)
//  blocks [4096, 8192): W int32 [K,N] -> fp16 (q-128) in [N,K], 64x64 tiles
// ---------------------------------------------------------------------------
__global__ void prep_kernel(const float* __restrict__ x,
                            const int* __restrict__ W,
                            const float* __restrict__ scale_p,
                            const float* __restrict__ zp_p,
                            const float* __restrict__ bias,
                            float* __restrict__ out) {
    __shared__ float red[256];
    __shared__ __half tile[64][66];
    const int tid = threadIdx.x;

    if (blockIdx.x < M_TOT) {
        const int m = blockIdx.x;
        const float4* xr = reinterpret_cast<const float4*>(x + (size_t)m * K_TOT);
        uint4* ar = reinterpret_cast<uint4*>(g_A + (size_t)m * K_TOT);
        float s = 0.0f;
        for (int i = tid; i < K_TOT / 8; i += 256) {
            float4 v0 = xr[2 * i];
            float4 v1 = xr[2 * i + 1];
            uint4 o;
            o.x = h2_bits(__floats2half2_rn(v0.x, v0.y));
            o.y = h2_bits(__floats2half2_rn(v0.z, v0.w));
            o.z = h2_bits(__floats2half2_rn(v1.x, v1.y));
            o.w = h2_bits(__floats2half2_rn(v1.z, v1.w));
            ar[i] = o;
            s += (v0.x + v0.y) + (v0.z + v0.w) + (v1.x + v1.y) + (v1.z + v1.w);
        }
        red[tid] = s;
        __syncthreads();
        for (int o = 128; o > 0; o >>= 1) {
            if (tid < o) red[tid] += red[tid + o];
            __syncthreads();
        }
        if (tid == 0) g_rowsum[m] = red[0];
        __syncthreads();
        // out pre-init: affine + bias (RED targets add onto this)
        const float ct = scale_p[0] * (128.0f - zp_p[0]) * red[0];
        const float4* b4 = reinterpret_cast<const float4*>(bias);
        float4* o4 = reinterpret_cast<float4*>(out + (size_t)m * N_TOT);
        for (int i = tid; i < N_TOT / 4; i += 256) {
            float4 bv = b4[i];
            bv.x += ct; bv.y += ct; bv.z += ct; bv.w += ct;
            o4[i] = bv;
        }
    } else {
        const int t  = blockIdx.x - M_TOT;
        const int n0 = (t & (N_TOT / 64 - 1)) * 64;
        const int k0 = (t / (N_TOT / 64)) * 64;

        const int2* W2 = reinterpret_cast<const int2*>(W);
        #pragma unroll
        for (int j = 0; j < 8; j++) {
            int idx2 = j * 256 + tid;
            int kr = idx2 >> 5;          // 0..63
            int nc2 = idx2 & 31;         // 0..31 (pairs)
            int2 v = W2[((size_t)(k0 + kr) * N_TOT + n0) / 2 + nc2];
            tile[2 * nc2][kr]     = __int2half_rn(v.x - 128);
            tile[2 * nc2 + 1][kr] = __int2half_rn(v.y - 128);
        }
        __syncthreads();
        #pragma unroll
        for (int j = 0; j < 8; j++) {
            int idx2 = j * 256 + tid;
            int nr = idx2 >> 5;          // 0..63
            int kc2 = idx2 & 31;         // 0..31 (pairs)
            __half2 v = *reinterpret_cast<__half2*>(&tile[nr][2 * kc2]);
            *reinterpret_cast<__half2*>(
                g_B + (size_t)(n0 + nr) * K_TOT + k0 + 2 * kc2) = v;
        }
    }
}

// ---------------------------------------------------------------------------
// GEMM: persistent stream-K. 296 CTAs x 128 threads, 2 CTAs/SM.
// Tile 128x128, BK=64; warp grid 2x2, warp tile 64x64; 3-stage mbarrier ring
// pipelining across tile boundaries.
// ---------------------------------------------------------------------------
static constexpr int BM = 128;
static constexpr int BN = 128;
static constexpr int BK = 64;           // 128 bytes per row
static constexpr int STAGES = 3;
static constexpr int NCHUNK = K_TOT / BK;                // 64 chunks per tile
static constexpr int TILES_N = N_TOT / BN;               // 32
static constexpr int G_TOT  = (M_TOT / BM) * TILES_N * NCHUNK;  // 65536
static constexpr int NCTA   = 296;
static constexpr int A_BYTES   = BM * 128;               // 16384
static constexpr int B_BYTES   = BN * 128;               // 16384
static constexpr int STG_BYTES = A_BYTES + B_BYTES;      // 32768
static constexpr int DYN_SMEM  = 1024 + STAGES * STG_BYTES;  // 99328
static constexpr int A_JOBS = BM * 8;                    // 1024 x 16B
static constexpr int JOBS   = (BM + BN) * 8;             // 2048 x 16B
static constexpr int NTHREADS = 128;

__global__ __launch_bounds__(NTHREADS, 2)
void gemm_kernel(const float* __restrict__ scale_p,
                 const float* __restrict__ bias,
                 float* __restrict__ out) {
    extern __shared__ char dyn_smem[];
    __shared__ __align__(16) unsigned long long s_bar[2 * STAGES];
    const uint32_t base = (smem_to_u32(dyn_smem) + 1023u) & ~1023u;
    const uint32_t barb = smem_to_u32(s_bar);

    const int tid  = threadIdx.x;
    const int lane = tid & 31;
    const int wid  = tid >> 5;          // 0..3
    const int warpM = wid & 1;          // 0..1 (64 rows each)
    const int warpN = wid >> 1;         // 0..1 (64 cols each)

    #define FULL_B(s)  (barb + (uint32_t)(s) * 8)
    #define EMPTY_B(s) (barb + (uint32_t)(STAGES + (s)) * 8)

    if (tid == 0) {
        #pragma unroll
        for (int s = 0; s < STAGES; s++) {
            MBAR_INIT(FULL_B(s), NTHREADS);
            MBAR_INIT(EMPTY_B(s), 4);
        }
    }
    __syncthreads();

    // global chunk range for this CTA
    const int gs = (int)(((long long)blockIdx.x * G_TOT) / NCTA);
    const int ge = (int)(((long long)(blockIdx.x + 1) * G_TOT) / NCTA);

    const int rowA = lane & 15;
    const int khA  = (lane >> 4) * 8;
    const int rowB = (lane & 7) + ((lane & 16) >> 1);
    const int khB  = ((lane >> 3) & 1) * 8;

    float acc[4][8][4];
    #pragma unroll
    for (int i = 0; i < 4; i++)
        #pragma unroll
        for (int j = 0; j < 8; j++)
            #pragma unroll
            for (int t = 0; t < 4; t++) acc[i][j][t] = 0.0f;

    // produce global chunk g into stage st
    auto issue_chunk = [&](int g, int st) {
        const int tile = g >> 6;
        const int mb = tile >> 5;       // tiles ordered mb-major: A reuse
        const int nb = tile & (TILES_N - 1);
        const int kofs = (g & (NCHUNK - 1)) * BK;
        const __half* Ab = g_A + (size_t)mb * BM * K_TOT;
        const __half* Bb = g_B + (size_t)nb * BN * K_TOT;
        const uint32_t sa = base + (uint32_t)st * STG_BYTES;
        const uint32_t sb = sa + A_BYTES;
        #pragma unroll
        for (int j = tid; j < JOBS; j += NTHREADS) {
            if (j < A_JOBS) {
                int r = j >> 3, cc = j & 7;
                uint32_t dst = sa + SWZ((uint32_t)(r * 128 + cc * 16));
                CP_ASYNC_16(dst, Ab + (size_t)r * K_TOT + kofs + cc * 8);
            } else {
                int jj = j - A_JOBS;
                int r = jj >> 3, cc = jj & 7;
                uint32_t dst = sb + SWZ((uint32_t)(r * 128 + cc * 16));
                CP_ASYNC_16(dst, Bb + (size_t)r * K_TOT + kofs + cc * 8);
            }
        }
        CP_ASYNC_MBAR_ARRIVE(FULL_B(st));
    };

    const float scale = scale_p[0];

    // cursors (R13 convention: producer empty-wait phase starts at 1)
    int p_st = 0, p_ph = 1;
    int c_st = 0, c_ph = 0;
    int p_g = gs;

    // prologue: produce first 2 chunks
    #pragma unroll
    for (int s = 0; s < STAGES - 1; s++) {
        MBAR_WAIT(EMPTY_B(p_st), p_ph);
        issue_chunk(p_g++, p_st);
        if (++p_st == STAGES) { p_st = 0; p_ph ^= 1; }
    }

    for (int g = gs; g < ge; g++) {
        MBAR_WAIT(FULL_B(c_st), c_ph);

        const uint32_t sa = base + (uint32_t)c_st * STG_BYTES;
        const uint32_t sb = sa + A_BYTES;

        #pragma unroll
        for (int ks = 0; ks < 4; ks++) {
            uint32_t b[4][4];
            #pragma unroll
            for (int q = 0; q < 4; q++) {
                uint32_t off = (uint32_t)((warpN * 64 + q * 16 + rowB) * 128 +
                                          (ks * 16 + khB) * 2);
                LDSM_X4(b[q][0], b[q][1], b[q][2], b[q][3], sb + SWZ(off));
            }
            #pragma unroll
            for (int mt = 0; mt < 4; mt++) {
                uint32_t a0, a1, a2, a3;
                uint32_t off = (uint32_t)((warpM * 64 + mt * 16 + rowA) * 128 +
                                          (ks * 16 + khA) * 2);
                LDSM_X4(a0, a1, a2, a3, sa + SWZ(off));
                #pragma unroll
                for (int q = 0; q < 4; q++) {
                    MMA16816(acc[mt][2 * q],     a0, a1, a2, a3, b[q][0], b[q][1]);
                    MMA16816(acc[mt][2 * q + 1], a0, a1, a2, a3, b[q][2], b[q][3]);
                }
            }
            // produce next chunk (possibly next tile) after ks=0's MMAs
            if (ks == 0 && p_g < ge) {
                MBAR_WAIT(EMPTY_B(p_st), p_ph);
                issue_chunk(p_g++, p_st);
                if (++p_st == STAGES) { p_st = 0; p_ph ^= 1; }
            }
        }

        if (lane == 0) MBAR_ARRIVE(EMPTY_B(c_st));
        if (++c_st == STAGES) { c_st = 0; c_ph ^= 1; }

        // ---- tile boundary: epilogue ----
        if ((g & (NCHUNK - 1)) == NCHUNK - 1 || g == ge - 1) {
            const int tile = g >> 6;
            const int t0 = tile << 6;
            const bool whole = (t0 >= gs) && (t0 + NCHUNK <= ge);
            const int mb = tile >> 5;
            const int nb = tile & (TILES_N - 1);
            const int mBase = mb * BM + warpM * 64;
            const int nBase = nb * BN + warpN * 64;

            #pragma unroll
            for (int mt = 0; mt < 4; mt++) {
                const int r0 = mBase + mt * 16 + (lane >> 2);
                const int r1 = r0 + 8;
                float* o0 = out + (size_t)r0 * N_TOT;
                float* o1 = out + (size_t)r1 * N_TOT;
                if (whole) {
                    const float kz = out ? 0.0f : 0.0f;  // (no-op; keep regs tight)
                    // direct store: scale*acc + (pre-init value components)
                    const float pre0 = 0.0f, pre1 = 0.0f;
                    (void)kz; (void)pre0; (void)pre1;
                    #pragma unroll
                    for (int nt = 0; nt < 8; nt++) {
                        const int col = nBase + nt * 8 + 2 * (lane & 3);
                        // read pre-init (bias + affine) and overwrite with sum
                        float2 p0 = *reinterpret_cast<const float2*>(o0 + col);
                        float2 p1 = *reinterpret_cast<const float2*>(o1 + col);
                        float2 v0, v1;
                        v0.x = fmaf(scale, acc[mt][nt][0], p0.x);
                        v0.y = fmaf(scale, acc[mt][nt][1], p0.y);
                        v1.x = fmaf(scale, acc[mt][nt][2], p1.x);
                        v1.y = fmaf(scale, acc[mt][nt][3], p1.y);
                        *reinterpret_cast<float2*>(o0 + col) = v0;
                        *reinterpret_cast<float2*>(o1 + col) = v1;
                    }
                } else {
                    #pragma unroll
                    for (int nt = 0; nt < 8; nt++) {
                        const int col = nBase + nt * 8 + 2 * (lane & 3);
                        REDG_ADD_F32(o0 + col,     scale * acc[mt][nt][0]);
                        REDG_ADD_F32(o0 + col + 1, scale * acc[mt][nt][1]);
                        REDG_ADD_F32(o1 + col,     scale * acc[mt][nt][2]);
                        REDG_ADD_F32(o1 + col + 1, scale * acc[mt][nt][3]);
                    }
                }
            }
            // reset accumulators for next tile
            #pragma unroll
            for (int i = 0; i < 4; i++)
                #pragma unroll
                for (int j = 0; j < 8; j++)
                    #pragma unroll
                    for (int t = 0; t < 4; t++) acc[i][j][t] = 0.0f;
        }
    }
    #undef FULL_B
    #undef EMPTY_B
}

// ---------------------------------------------------------------------------
extern "C" void kernel_launch(void* const* d_in, const int* in_sizes, int n_in,
                              void* d_out, int out_size) {
    const float* x     = (const float*)d_in[0];
    const int*   q     = (const int*)d_in[1];
    const float* scale = (const float*)d_in[2];
    const float* zp    = (const float*)d_in[3];
    const float* bias  = (const float*)d_in[4];
    float* out = (float*)d_out;

    cudaFuncSetAttribute(gemm_kernel,
                         cudaFuncAttributeMaxDynamicSharedMemorySize, DYN_SMEM);

    prep_kernel<<<M_TOT + (K_TOT / 64) * (N_TOT / 64), 256>>>(
        x, q, scale, zp, bias, out);
    gemm_kernel<<<NCTA, NTHREADS, DYN_SMEM>>>(scale, bias, out);
}

// round 15
// speedup vs baseline: 1.1581x; 1.1581x over previous
#include <cuda_runtime.h>
#include <cuda_fp16.h>
#include <cstdint>

// ============================================================================
// y[m,n] = sum_k x[m,k] * ((q[k,n]-zp)*scale) + bias[n]
// Decomposition: W = scale*(q-128) + scale*(128-zp);  (q-128) exact in fp16.
// R15 = R12 (best measured structure: 1024 CTAs, 128 thr, 2 CTAs/SM,
//   BM=BN=128, BK=64, warp tile 64x64, 3-stage cp.async + per-chunk
//   rendezvous, deferred next-stage copy after ks=0)
//   + A-fragment double-buffer across the mt loop: the (ks,mt+1) A-ldmatrix
//   issues during mt's 8 MMAs, removing the per-mt LDS->MMA dependency chain.
// ============================================================================

#define M_TOT 4096
#define N_TOT 4096
#define K_TOT 4096

__device__ __align__(256) __half g_A[(size_t)M_TOT * K_TOT]; // x fp16 [M,K]
__device__ __align__(256) __half g_B[(size_t)N_TOT * K_TOT]; // (q-128) fp16 [N,K]
__device__ float g_rowsum[M_TOT];

// ---------------------------------------------------------------------------
__device__ __forceinline__ uint32_t smem_to_u32(const void* p) {
    uint32_t a;
    asm("{ .reg .u64 t; cvta.to.shared.u64 t, %1; cvt.u32.u64 %0, t; }"
        : "=r"(a) : "l"(p));
    return a;
}

__device__ __forceinline__ uint32_t h2_bits(__half2 h) {
    return *reinterpret_cast<uint32_t*>(&h);
}

#define SWZ(o) ((o) ^ (((o) >> 3) & 0x70))

#define CP_ASYNC_16(dst, src) \
    asm volatile("cp.async.cg.shared.global [%0], [%1], 16;" \
                 :: "r"(dst), "l"(src) : "memory")
#define CP_COMMIT() asm volatile("cp.async.commit_group;" ::: "memory")
#define CP_WAIT(n)  asm volatile("cp.async.wait_group %0;" :: "n"(n) : "memory")

#define LDSM_X4(R0, R1, R2, R3, ADDR) \
    asm volatile("ldmatrix.sync.aligned.m8n8.x4.shared.b16 {%0,%1,%2,%3}, [%4];" \
                 : "=r"(R0), "=r"(R1), "=r"(R2), "=r"(R3) : "r"(ADDR))

#define MMA16816(C, A0, A1, A2, A3, B0, B1) \
    asm volatile("mma.sync.aligned.m16n8k16.row.col.f32.f16.f16.f32 " \
                 "{%0,%1,%2,%3}, {%4,%5,%6,%7}, {%8,%9}, {%0,%1,%2,%3};" \
                 : "+f"((C)[0]), "+f"((C)[1]), "+f"((C)[2]), "+f"((C)[3]) \
                 : "r"(A0), "r"(A1), "r"(A2), "r"(A3), "r"(B0), "r"(B1))

// ---------------------------------------------------------------------------
// Merged prep (one launch).
//  blocks [0, 4096): x row -> fp16 (16B stores) + rowsum
//  blocks [4096, 8192): W int32 [K,N] -> fp16 (q-128) in [N,K], 64x64 tiles
// ---------------------------------------------------------------------------
__global__ void prep_kernel(const float* __restrict__ x,
                            const int* __restrict__ W) {
    __shared__ float red[256];
    __shared__ __half tile[64][66];
    const int tid = threadIdx.x;

    if (blockIdx.x < M_TOT) {
        const int m = blockIdx.x;
        const float4* xr = reinterpret_cast<const float4*>(x + (size_t)m * K_TOT);
        uint4* ar = reinterpret_cast<uint4*>(g_A + (size_t)m * K_TOT);
        float s = 0.0f;
        for (int i = tid; i < K_TOT / 8; i += 256) {
            float4 v0 = xr[2 * i];
            float4 v1 = xr[2 * i + 1];
            uint4 o;
            o.x = h2_bits(__floats2half2_rn(v0.x, v0.y));
            o.y = h2_bits(__floats2half2_rn(v0.z, v0.w));
            o.z = h2_bits(__floats2half2_rn(v1.x, v1.y));
            o.w = h2_bits(__floats2half2_rn(v1.z, v1.w));
            ar[i] = o;
            s += (v0.x + v0.y) + (v0.z + v0.w) + (v1.x + v1.y) + (v1.z + v1.w);
        }
        red[tid] = s;
        __syncthreads();
        for (int o = 128; o > 0; o >>= 1) {
            if (tid < o) red[tid] += red[tid + o];
            __syncthreads();
        }
        if (tid == 0) g_rowsum[m] = red[0];
    } else {
        const int t  = blockIdx.x - M_TOT;
        const int n0 = (t & (N_TOT / 64 - 1)) * 64;
        const int k0 = (t / (N_TOT / 64)) * 64;

        const int2* W2 = reinterpret_cast<const int2*>(W);
        #pragma unroll
        for (int j = 0; j < 8; j++) {
            int idx2 = j * 256 + tid;
            int kr = idx2 >> 5;          // 0..63
            int nc2 = idx2 & 31;         // 0..31 (pairs)
            int2 v = W2[((size_t)(k0 + kr) * N_TOT + n0) / 2 + nc2];
            tile[2 * nc2][kr]     = __int2half_rn(v.x - 128);
            tile[2 * nc2 + 1][kr] = __int2half_rn(v.y - 128);
        }
        __syncthreads();
        #pragma unroll
        for (int j = 0; j < 8; j++) {
            int idx2 = j * 256 + tid;
            int nr = idx2 >> 5;          // 0..63
            int kc2 = idx2 & 31;         // 0..31 (pairs)
            __half2 v = *reinterpret_cast<__half2*>(&tile[nr][2 * kc2]);
            *reinterpret_cast<__half2*>(
                g_B + (size_t)(n0 + nr) * K_TOT + k0 + 2 * kc2) = v;
        }
    }
}

// ---------------------------------------------------------------------------
// GEMM: BM=128, BN=128, BK=64, 3-stage cp.async, 128 threads (4 warps),
// 2 CTAs/SM. Warp grid 2(M) x 2(N); warp tile 64x64. A-frag double-buffer.
// ---------------------------------------------------------------------------
static constexpr int BM = 128;
static constexpr int BN = 128;
static constexpr int BK = 64;           // 128 bytes per row
static constexpr int STAGES = 3;
static constexpr int NCHUNK = K_TOT / BK;                // 64
static constexpr int A_BYTES   = BM * 128;               // 16384
static constexpr int B_BYTES   = BN * 128;               // 16384
static constexpr int STG_BYTES = A_BYTES + B_BYTES;      // 32768
static constexpr int DYN_SMEM  = 1024 + STAGES * STG_BYTES;  // 99328
static constexpr int A_JOBS = BM * 8;                    // 1024 x 16B
static constexpr int JOBS   = (BM + BN) * 8;             // 2048 x 16B
static constexpr int NTHREADS = 128;

__global__ __launch_bounds__(NTHREADS, 2)
void gemm_kernel(const float* __restrict__ scale_p,
                 const float* __restrict__ zp_p,
                 const float* __restrict__ bias,
                 float* __restrict__ out) {
    extern __shared__ char dyn_smem[];
    const uint32_t base = (smem_to_u32(dyn_smem) + 1023u) & ~1023u;

    const int tid  = threadIdx.x;
    const int lane = tid & 31;
    const int wid  = tid >> 5;          // 0..3
    const int warpM = wid & 1;          // 0..1 (64 rows each)
    const int warpN = wid >> 1;         // 0..1 (64 cols each)

    const __half* Abase = g_A + (size_t)(blockIdx.y * BM) * K_TOT;
    const __half* Bbase = g_B + (size_t)(blockIdx.x * BN) * K_TOT;

    const int rowA = lane & 15;                       // A rows within m16
    const int khA  = (lane >> 4) * 8;                 // A k-half
    const int rowB = (lane & 7) + ((lane & 16) >> 1); // B n within n16
    const int khB  = ((lane >> 3) & 1) * 8;           // B k-half

    float acc[4][8][4];  // [mt 4 x m16][nt 8 x n8][frag] = 128 regs
    #pragma unroll
    for (int i = 0; i < 4; i++)
        #pragma unroll
        for (int j = 0; j < 8; j++)
            #pragma unroll
            for (int t = 0; t < 4; t++) acc[i][j][t] = 0.0f;

    auto load_stage = [&](int c, int st) {
        const int kofs = c * BK;
        const uint32_t sa = base + (uint32_t)st * STG_BYTES;
        const uint32_t sb = sa + A_BYTES;
        #pragma unroll
        for (int j = tid; j < JOBS; j += NTHREADS) {
            if (j < A_JOBS) {
                int r = j >> 3, cc = j & 7;
                uint32_t dst = sa + SWZ((uint32_t)(r * 128 + cc * 16));
                CP_ASYNC_16(dst, Abase + (size_t)r * K_TOT + kofs + cc * 8);
            } else {
                int jj = j - A_JOBS;
                int r = jj >> 3, cc = jj & 7;
                uint32_t dst = sb + SWZ((uint32_t)(r * 128 + cc * 16));
                CP_ASYNC_16(dst, Bbase + (size_t)r * K_TOT + kofs + cc * 8);
            }
        }
    };

    // A-fragment smem offset for (ks, mt), pre-swizzled
    auto a_off = [&](int ks, int mt) -> uint32_t {
        return SWZ((uint32_t)((warpM * 64 + mt * 16 + rowA) * 128 +
                              (ks * 16 + khA) * 2));
    };

    // prologue: fill STAGES-1 = 2 stages
    #pragma unroll
    for (int s = 0; s < STAGES - 1; s++) {
        load_stage(s, s);
        CP_COMMIT();
    }

    int st = 0, pst = STAGES - 1;
    for (int c = 0; c < NCHUNK; c++) {
        CP_WAIT(STAGES - 2);
        __syncthreads();   // all reads of stage pst complete; stage st ready

        const uint32_t sa = base + (uint32_t)st * STG_BYTES;
        const uint32_t sb = sa + A_BYTES;

        // prime A double-buffer with (ks=0, mt=0)
        uint32_t ac[4], an[4];
        LDSM_X4(ac[0], ac[1], ac[2], ac[3], sa + a_off(0, 0));

        #pragma unroll
        for (int ks = 0; ks < 4; ks++) {
            // B fragments for this ks (latency overlapped by prior ks's MMAs)
            uint32_t b[4][4];
            #pragma unroll
            for (int q = 0; q < 4; q++) {
                uint32_t off = (uint32_t)((warpN * 64 + q * 16 + rowB) * 128 +
                                          (ks * 16 + khB) * 2);
                LDSM_X4(b[q][0], b[q][1], b[q][2], b[q][3], sb + SWZ(off));
            }
            #pragma unroll
            for (int mt = 0; mt < 4; mt++) {
                // prefetch next A fragment while this mt's MMAs issue
                if (mt < 3) {
                    LDSM_X4(an[0], an[1], an[2], an[3], sa + a_off(ks, mt + 1));
                } else if (ks < 3) {
                    LDSM_X4(an[0], an[1], an[2], an[3], sa + a_off(ks + 1, 0));
                }
                #pragma unroll
                for (int q = 0; q < 4; q++) {
                    MMA16816(acc[mt][2 * q],     ac[0], ac[1], ac[2], ac[3],
                             b[q][0], b[q][1]);
                    MMA16816(acc[mt][2 * q + 1], ac[0], ac[1], ac[2], ac[3],
                             b[q][2], b[q][3]);
                }
                #pragma unroll
                for (int t = 0; t < 4; t++) { uint32_t tmp = ac[t]; ac[t] = an[t]; an[t] = tmp; }
            }
            // Deferred next-stage copy after ks=0's MMAs (R8/R12 pattern).
            if (ks == 0) {
                if (c + STAGES - 1 < NCHUNK) load_stage(c + STAGES - 1, pst);
                CP_COMMIT();
            }
        }
        pst = st;
        st = (st + 1 == STAGES) ? 0 : st + 1;
    }

    // ---- epilogue ----
    const float scale = scale_p[0];
    const float zp    = zp_p[0];
    const float kz    = scale * (128.0f - zp);
    const int mBase = blockIdx.y * BM + warpM * 64;
    const int nBase = blockIdx.x * BN + warpN * 64;

    #pragma unroll
    for (int mt = 0; mt < 4; mt++) {
        const int r0 = mBase + mt * 16 + (lane >> 2);
        const int r1 = r0 + 8;
        const float ct0 = kz * g_rowsum[r0];
        const float ct1 = kz * g_rowsum[r1];
        float* o0 = out + (size_t)r0 * N_TOT;
        float* o1 = out + (size_t)r1 * N_TOT;
        #pragma unroll
        for (int nt = 0; nt < 8; nt++) {
            const int col = nBase + nt * 8 + 2 * (lane & 3);
            const float2 bv = *reinterpret_cast<const float2*>(bias + col);
            float2 v0, v1;
            v0.x = fmaf(scale, acc[mt][nt][0], ct0 + bv.x);
            v0.y = fmaf(scale, acc[mt][nt][1], ct0 + bv.y);
            v1.x = fmaf(scale, acc[mt][nt][2], ct1 + bv.x);
            v1.y = fmaf(scale, acc[mt][nt][3], ct1 + bv.y);
            *reinterpret_cast<float2*>(o0 + col) = v0;
            *reinterpret_cast<float2*>(o1 + col) = v1;
        }
    }
}

// ---------------------------------------------------------------------------
extern "C" void kernel_launch(void* const* d_in, const int* in_sizes, int n_in,
                              void* d_out, int out_size) {
    const float* x     = (const float*)d_in[0];
    const int*   q     = (const int*)d_in[1];
    const float* scale = (const float*)d_in[2];
    const float* zp    = (const float*)d_in[3];
    const float* bias  = (const float*)d_in[4];
    float* out = (float*)d_out;

    cudaFuncSetAttribute(gemm_kernel,
                         cudaFuncAttributeMaxDynamicSharedMemorySize, DYN_SMEM);

    prep_kernel<<<M_TOT + (K_TOT / 64) * (N_TOT / 64), 256>>>(x, q);
    gemm_kernel<<<dim3(N_TOT / BN, M_TOT / BM), NTHREADS, DYN_SMEM>>>(
        scale, zp, bias, out);
}